// round 12
// baseline (speedup 1.0000x reference)
#include <cuda_runtime.h>
#include <cstdint>

// Holonomy: out[b,l] = M_15 @ ... @ M_1 @ M_0,  M_t = Gamma[b, loops[l][t+1], loops[l][t]]
// Gamma: [4, 512, 512, 8, 8] fp32; loops: [64, 17] int (32 or 64 bit); out: [4,64,8,8] fp32.
//
// One WARP per chain; fully warp-synchronous. Lane r*8+c (r=0..3, c=0..7)
// holds elements (r,c) and (r+4,c) of each 8x8 matrix — a layout closed under
// the shuffle-matmul, so the 15 products are evaluated as a balanced TREE
// (depth 4) instead of a serial left-fold (depth 15): same instruction count,
// ~3.7x less dependent latency, shuffle latency hidden by the 8-way ILP of
// the first tree level.
//
// loops dtype detected per-warp: int64 data (values < 2^31) has every odd
// 32-bit word zero; 32 sampled odd words all-zero under int32 random data
// in [0,512) has probability 512^-32.

#define BATCH   4
#define SEQ     512
#define NLOOPS  64
#define LOOPLEN 17
#define NSTEPS  (LOOPLEN - 1)    // 16
#define NCHAINS (BATCH * NLOOPS) // 256
#define WARPS_PER_BLOCK 4
#define FULLMASK 0xffffffffu

// P = A @ B, all matrices in the (r,c)/(r+4,c) two-register lane layout.
// k-loop split in halves so no select sits on the critical path.
__device__ __forceinline__ void mm8(float a0, float a1, float b0, float b1,
                                    int r, int c, float& n0, float& n1)
{
    float s0 = 0.f, s1 = 0.f;
    #pragma unroll
    for (int k = 0; k < 4; k++) {           // A[.,k], B[k][c] from b0
        const float x0 = __shfl_sync(FULLMASK, a0, r * 8 + k);
        const float x1 = __shfl_sync(FULLMASK, a1, r * 8 + k);
        const float bk = __shfl_sync(FULLMASK, b0, k * 8 + c);
        s0 = fmaf(x0, bk, s0);
        s1 = fmaf(x1, bk, s1);
    }
    #pragma unroll
    for (int k = 0; k < 4; k++) {           // A[.,4+k], B[4+k][c] from b1
        const float x0 = __shfl_sync(FULLMASK, a0, r * 8 + 4 + k);
        const float x1 = __shfl_sync(FULLMASK, a1, r * 8 + 4 + k);
        const float bk = __shfl_sync(FULLMASK, b1, k * 8 + c);
        s0 = fmaf(x0, bk, s0);
        s1 = fmaf(x1, bk, s1);
    }
    n0 = s0;
    n1 = s1;
}

__global__ void __launch_bounds__(32 * WARPS_PER_BLOCK, 8) holonomy_kernel(
    const float* __restrict__ Gamma,
    const int*   __restrict__ loops_w,   // raw 32-bit view of loops buffer
    float* __restrict__ out)
{
    const int lane = threadIdx.x & 31;
    const int w    = blockIdx.x * WARPS_PER_BLOCK + (threadIdx.x >> 5); // chain 0..255
    const int b    = w >> 6;
    const int r    = lane >> 3;        // 0..3
    const int c    = lane & 7;         // 0..7

    // ---- issue ALL front-end loads concurrently (one memory round trip) ----
    const int det = loops_w[2 * lane + 1];            // words 1..63: in-bounds for both dtypes
    const int l   = w & (NLOOPS - 1);
    const int e   = l * LOOPLEN + (lane < LOOPLEN ? lane : LOOPLEN - 1);
    const int c32 = loops_w[e];                       // int32 interpretation
    const int c64 = loops_w[2 * e];                   // int64 (low word) interpretation

    const unsigned nz = __ballot_sync(FULLMASK, det != 0);
    const int v = ((nz == 0u) ? c64 : c32) & (SEQ - 1);   // defensive mask: never OOB

    // distribute loop indices to all lanes
    int idx[LOOPLEN];
    #pragma unroll
    for (int t = 0; t < LOOPLEN; t++)
        idx[t] = __shfl_sync(FULLMASK, v, t);

    // ---- gather all 16 matrices into registers (32 coalesced LDG, MLP=32) ----
    const float* Gb = Gamma + (size_t)b * (SEQ * SEQ * 64);
    float Ma0[NSTEPS], Ma1[NSTEPS];
    #pragma unroll
    for (int t = 0; t < NSTEPS; t++) {
        const float* p = Gb + ((size_t)idx[t + 1] * SEQ + idx[t]) * 64;
        Ma0[t] = p[lane];        // element (r,   c)
        Ma1[t] = p[32 + lane];   // element (r+4, c)
    }

    // ---- balanced tree product (in place, ascending composition) ----
    // level 1: Ma[2i]   <- Ma[2i+1] @ Ma[2i]      (8 independent matmuls)
    #pragma unroll
    for (int i = 0; i < 8; i++)
        mm8(Ma0[2*i+1], Ma1[2*i+1], Ma0[2*i], Ma1[2*i], r, c, Ma0[2*i], Ma1[2*i]);
    // level 2: Ma[4i]   <- Ma[4i+2] @ Ma[4i]      (4 independent)
    #pragma unroll
    for (int i = 0; i < 4; i++)
        mm8(Ma0[4*i+2], Ma1[4*i+2], Ma0[4*i], Ma1[4*i], r, c, Ma0[4*i], Ma1[4*i]);
    // level 3: Ma[8i]   <- Ma[8i+4] @ Ma[8i]      (2 independent)
    #pragma unroll
    for (int i = 0; i < 2; i++)
        mm8(Ma0[8*i+4], Ma1[8*i+4], Ma0[8*i], Ma1[8*i], r, c, Ma0[8*i], Ma1[8*i]);
    // level 4: Ma[0]    <- Ma[8] @ Ma[0]          == M15 ... M0
    mm8(Ma0[8], Ma1[8], Ma0[0], Ma1[0], r, c, Ma0[0], Ma1[0]);

    float* o = out + (size_t)w * 64;
    o[lane]      = Ma0[0];
    o[32 + lane] = Ma1[0];
}

extern "C" void kernel_launch(void* const* d_in, const int* in_sizes, int n_in,
                              void* d_out, int out_size)
{
    // Defensive input-order resolution via element counts:
    // Gamma = 67,108,864 elems; loops = 1088 elems.
    int gi = 0, li = 1;
    if (n_in >= 2 && in_sizes[0] < in_sizes[1]) { gi = 1; li = 0; }

    const float* Gamma   = (const float*)d_in[gi];
    const int*   loops_w = (const int*)d_in[li];
    float*       out     = (float*)d_out;

    holonomy_kernel<<<NCHAINS / WARPS_PER_BLOCK, 32 * WARPS_PER_BLOCK>>>(Gamma, loops_w, out);
}

// round 15
// speedup vs baseline: 1.0385x; 1.0385x over previous
#include <cuda_runtime.h>
#include <cstdint>

// Holonomy: out[b,l] = M_15 @ ... @ M_1 @ M_0,  M_t = Gamma[b, loops[l][t+1], loops[l][t]]
// Gamma: [4, 512, 512, 8, 8] fp32; loops: [64, 17] int (32 or 64 bit); out: [4,64,8,8] fp32.
//
// One WARP per chain; fully warp-synchronous, no smem, no barriers.
// float2 layout: lane L holds flat elements 2L and 2L+1 of each 8x8 matrix,
// i.e. M[row][col], M[row][col+1] with row = L>>2, col = (L&3)*2.
// This layout is closed under the shuffle-matmul (A-element register pick is
// compile-time since k is unrolled), and makes every gather a single LDG.64.
// The 15 products are evaluated as a balanced TREE (depth 4, not 15).
//
// loops dtype detected per-warp: int64 data (values < 2^31) has every odd
// 32-bit word zero; 32 sampled odd words all-zero under int32 random data
// in [0,512) has probability 512^-32.

#define BATCH   4
#define SEQ     512
#define NLOOPS  64
#define LOOPLEN 17
#define NSTEPS  (LOOPLEN - 1)    // 16
#define NCHAINS (BATCH * NLOOPS) // 256
#define WARPS_PER_BLOCK 4
#define FULLMASK 0xffffffffu

// P = A @ B in the float2 lane layout. row = lane>>2, cq = lane&3.
__device__ __forceinline__ float2 mm8(float2 a, float2 bm, int row, int cq)
{
    float s0 = 0.f, s1 = 0.f;
    #pragma unroll
    for (int k = 0; k < 8; k++) {
        // A[row][k]      -> lane row*4 + (k>>1), element k&1 (compile-time pick)
        // B[k][col + d]  -> lane k*4 + cq,       element d
        const float av = __shfl_sync(FULLMASK, (k & 1) ? a.y : a.x, row * 4 + (k >> 1));
        const float b0 = __shfl_sync(FULLMASK, bm.x, k * 4 + cq);
        const float b1 = __shfl_sync(FULLMASK, bm.y, k * 4 + cq);
        s0 = fmaf(av, b0, s0);
        s1 = fmaf(av, b1, s1);
    }
    return make_float2(s0, s1);
}

__global__ void __launch_bounds__(32 * WARPS_PER_BLOCK, 8) holonomy_kernel(
    const float* __restrict__ Gamma,
    const int*   __restrict__ loops_w,   // raw 32-bit view of loops buffer
    float* __restrict__ out)
{
    const int lane = threadIdx.x & 31;
    const int w    = blockIdx.x * WARPS_PER_BLOCK + (threadIdx.x >> 5); // chain 0..255
    const int b    = w >> 6;
    const int row  = lane >> 2;        // 0..7
    const int cq   = lane & 3;         // column pair 0..3

    // ---- issue ALL front-end loads concurrently (one memory round trip) ----
    const int det = loops_w[2 * lane + 1];            // words 1..63: in-bounds for both dtypes
    const int l   = w & (NLOOPS - 1);
    const int e   = l * LOOPLEN + (lane < LOOPLEN ? lane : LOOPLEN - 1);
    const int c32 = loops_w[e];                       // int32 interpretation
    const int c64 = loops_w[2 * e];                   // int64 (low word) interpretation

    const unsigned nz = __ballot_sync(FULLMASK, det != 0);
    const int v = ((nz == 0u) ? c64 : c32) & (SEQ - 1);   // defensive mask: never OOB

    // lane t (t < 16) computes the element offset of matrix t once
    const int vn  = __shfl_down_sync(FULLMASK, v, 1);     // idx[t+1]
    const int ofs = (vn * SEQ + v) * 64;                  // < 2^25, fits int

    // ---- gather all 16 matrices: one coalesced LDG.64 per matrix ----
    const float2* Gb = (const float2*)(Gamma + (size_t)b * (SEQ * SEQ * 64));
    float2 Mt[NSTEPS];
    #pragma unroll
    for (int t = 0; t < NSTEPS; t++) {
        const int o = __shfl_sync(FULLMASK, ofs, t);
        Mt[t] = Gb[(o >> 1) + lane];
    }

    // ---- balanced tree product (in place, ascending composition) ----
    #pragma unroll
    for (int i = 0; i < 8; i++)   // level 1: 8 independent matmuls
        Mt[2*i] = mm8(Mt[2*i+1], Mt[2*i], row, cq);
    #pragma unroll
    for (int i = 0; i < 4; i++)   // level 2
        Mt[4*i] = mm8(Mt[4*i+2], Mt[4*i], row, cq);
    #pragma unroll
    for (int i = 0; i < 2; i++)   // level 3
        Mt[8*i] = mm8(Mt[8*i+4], Mt[8*i], row, cq);
    Mt[0] = mm8(Mt[8], Mt[0], row, cq);   // level 4 == M15 ... M0

    ((float2*)(out + (size_t)w * 64))[lane] = Mt[0];
}

extern "C" void kernel_launch(void* const* d_in, const int* in_sizes, int n_in,
                              void* d_out, int out_size)
{
    // Defensive input-order resolution via element counts:
    // Gamma = 67,108,864 elems; loops = 1088 elems.
    int gi = 0, li = 1;
    if (n_in >= 2 && in_sizes[0] < in_sizes[1]) { gi = 1; li = 0; }

    const float* Gamma   = (const float*)d_in[gi];
    const int*   loops_w = (const int*)d_in[li];
    float*       out     = (float*)d_out;

    holonomy_kernel<<<NCHAINS / WARPS_PER_BLOCK, 32 * WARPS_PER_BLOCK>>>(Gamma, loops_w, out);
}